// round 17
// baseline (speedup 1.0000x reference)
#include <cuda_runtime.h>
#include <cuda_fp16.h>
#include <math.h>
#include <cstdint>

#define NN 50000
#define EE 800000
#define DD 128
#define PAD 272                 // padded smem row stride (bytes): conflict-free ldmatrix
#define SA 0
#define SW 34816
#define SM_TOT 69632
#define CHUNK 1024

// ---- scratch (__device__ globals; allocation-free rule) ----
__device__ __half g_hwsh[(size_t)NN * DD];   // (h@W)*dinv, fp16 (gather payload)
__device__ __half g_aggh[(size_t)NN * DD];   // relu(aggregate), fp16 (next-layer input)
__device__ int    g_count[NN];
__device__ float  g_dinv[NN];
__device__ int    g_rowptr[NN];              // segment start (arrival-ordered)
__device__ int    g_cursor[NN];
__device__ int    g_adj[EE];
__device__ int    g_scanbase;                // global cursor for chunk bases
__device__ __half g_wt[3 * DD * DD];         // W^T fp16 ([n][k] row-major)

// ---- helpers ----
__device__ __forceinline__ uint32_t smem_u32(const void* p) {
    uint32_t a;
    asm("{ .reg .u64 t; cvta.to.shared.u64 t, %1; cvt.u32.u64 %0, t; }" : "=r"(a) : "l"(p));
    return a;
}
__device__ __forceinline__ void ldsm4(uint32_t* r, uint32_t addr) {
    asm volatile("ldmatrix.sync.aligned.m8n8.x4.shared.b16 {%0,%1,%2,%3}, [%4];"
                 : "=r"(r[0]), "=r"(r[1]), "=r"(r[2]), "=r"(r[3]) : "r"(addr));
}
__device__ __forceinline__ void mma_f16(float* c, const uint32_t* a, uint32_t b0, uint32_t b1) {
    asm volatile("mma.sync.aligned.m16n8k16.row.col.f32.f16.f16.f32 "
                 "{%0,%1,%2,%3}, {%4,%5,%6,%7}, {%8,%9}, {%0,%1,%2,%3};"
                 : "+f"(c[0]), "+f"(c[1]), "+f"(c[2]), "+f"(c[3])
                 : "r"(a[0]), "r"(a[1]), "r"(a[2]), "r"(a[3]), "r"(b0), "r"(b1));
}
__device__ __forceinline__ void add8(float* a, uint4 v) {
    const __half2* h = reinterpret_cast<const __half2*>(&v);
#pragma unroll
    for (int i = 0; i < 4; i++) {
        float2 f = __half22float2(h[i]);
        a[2 * i] += f.x;
        a[2 * i + 1] += f.y;
    }
}

// ---------------------------------------------------------------------------
// GEMM building blocks (verified round-13 code, refactored into functions)
// ---------------------------------------------------------------------------
__device__ __forceinline__ void stage_w(char* smem, int tid, const __half* __restrict__ wt) {
    const float4* w4 = reinterpret_cast<const float4*>(wt);
#pragma unroll
    for (int i = 0; i < 8; i++) {
        int chunk = i * 256 + tid;
        int r = chunk >> 4, c = chunk & 15;
        *reinterpret_cast<float4*>(smem + SW + r * PAD + c * 16) = w4[chunk];
    }
}

__device__ __forceinline__ void stage_a_f32(char* smem, int tid, const float* __restrict__ Hf,
                                            int row0, int n) {
    const float4* H4 = reinterpret_cast<const float4*>(Hf);
    const int maxc = (n - row0) * 32;
#pragma unroll
    for (int i = 0; i < 16; i++) {
        int chunk = i * 256 + tid;
        int r = chunk >> 5, c = chunk & 31;
        float4 v = make_float4(0.f, 0.f, 0.f, 0.f);
        if (chunk < maxc) v = H4[(size_t)row0 * 32 + chunk];
        __half2 h01 = __floats2half2_rn(v.x, v.y);
        __half2 h23 = __floats2half2_rn(v.z, v.w);
        uint2 hp;
        hp.x = *reinterpret_cast<uint32_t*>(&h01);
        hp.y = *reinterpret_cast<uint32_t*>(&h23);
        *reinterpret_cast<uint2*>(smem + SA + r * PAD + c * 8) = hp;
    }
}

__device__ __forceinline__ void stage_a_f16(char* smem, int tid, const __half* __restrict__ Hh,
                                            int row0, int n) {
    const uint4* H4 = reinterpret_cast<const uint4*>(Hh);
    const int maxc = (n - row0) * 16;
#pragma unroll
    for (int i = 0; i < 8; i++) {
        int chunk = i * 256 + tid;
        int r = chunk >> 4, c = chunk & 15;
        uint4 v = make_uint4(0u, 0u, 0u, 0u);
        if (chunk < maxc) v = H4[(size_t)row0 * 16 + chunk];
        *reinterpret_cast<uint4*>(smem + SA + r * PAD + c * 16) = v;
    }
}

__device__ __forceinline__ void gemm_core(char* smem, int tid, int row0,
                                          const float* __restrict__ dinv,
                                          __half* __restrict__ hws, int n) {
    const uint32_t sb = smem_u32(smem);
    const int w = tid >> 5, lane = tid & 31;
    const int mg = w >> 1, cg = w & 1;
    const int g = lane >> 2, tg = lane & 3;

    const uint32_t aAddr = sb + SA +
        (uint32_t)(mg * 32 + (lane & 15)) * PAD + (uint32_t)(lane >> 4) * 16;
    const uint32_t bAddr = sb + SW +
        (uint32_t)(cg * 64 + ((lane >> 4) & 1) * 8 + (lane & 7)) * PAD +
        (uint32_t)((lane >> 3) & 1) * 16;

    float acc[16][4];
#pragma unroll
    for (int t = 0; t < 16; t++)
#pragma unroll
        for (int j = 0; j < 4; j++) acc[t][j] = 0.f;

#pragma unroll
    for (int kk = 0; kk < 8; kk++) {
        uint32_t a0[4], a1[4];
        ldsm4(a0, aAddr + kk * 32);
        ldsm4(a1, aAddr + 16 * PAD + kk * 32);
#pragma unroll
        for (int np = 0; np < 4; np++) {
            uint32_t b[4];
            ldsm4(b, bAddr + (uint32_t)np * (16 * PAD) + kk * 32);
            mma_f16(acc[np * 2 + 0], a0, b[0], b[1]);
            mma_f16(acc[np * 2 + 1], a0, b[2], b[3]);
            mma_f16(acc[8 + np * 2 + 0], a1, b[0], b[1]);
            mma_f16(acc[8 + np * 2 + 1], a1, b[2], b[3]);
        }
    }

    const int rbase = row0 + mg * 32 + g;
#pragma unroll
    for (int ms = 0; ms < 2; ms++) {
        const int rA = rbase + ms * 16;
        const int rB = rA + 8;
        const float diA = (rA < n) ? dinv[rA] : 0.f;
        const float diB = (rB < n) ? dinv[rB] : 0.f;
#pragma unroll
        for (int np = 0; np < 4; np++) {
#pragma unroll
            for (int h = 0; h < 2; h++) {
                const float* cf = acc[ms * 8 + np * 2 + h];
                const int col = cg * 64 + np * 16 + h * 8 + tg * 2;
                if (rA < n) {
                    __half2 hv = __floats2half2_rn(cf[0] * diA, cf[1] * diA);
                    *reinterpret_cast<__half2*>(hws + (size_t)rA * DD + col) = hv;
                }
                if (rB < n) {
                    __half2 hv = __floats2half2_rn(cf[2] * diB, cf[3] * diB);
                    *reinterpret_cast<__half2*>(hws + (size_t)rB * DD + col) = hv;
                }
            }
        }
    }
}

// ---------------------------------------------------------------------------
// fatA: blocks [0,192) convert W (3 layers) to fp16 W^T; remaining blocks
// count in-degrees (g_count pre-zeroed by cudaMemsetAsync). Independent work.
// ---------------------------------------------------------------------------
__global__ void k_fatA(const float* __restrict__ W0, const float* __restrict__ W1,
                       const float* __restrict__ W2, __half* __restrict__ wt,
                       const int* __restrict__ dst, int e) {
    const int bid = blockIdx.x, tid = threadIdx.x;
    if (bid < 192) {
        int gi = bid * 256 + tid;                 // < 3*16384 exactly
        int layer = gi >> 14, idx = gi & 16383;
        const float* W = (layer == 0) ? W0 : (layer == 1) ? W1 : W2;
        int k = idx >> 7, nn = idx & 127;
        wt[layer * DD * DD + nn * DD + k] = __float2half(W[idx]);
        if (gi == 0) g_scanbase = 0;
    } else {
        int i = (bid - 192) * 256 + tid;
        const int stride = (gridDim.x - 192) * 256;
        for (; i < e; i += stride) atomicAdd(&g_count[dst[i]], 1);
    }
}

// One-pass offsets: per-chunk smem scan; chunk base via atomicAdd (arrival
// order — valid because consumers read (rowptr[w], count[w]), not rowptr[w+1]).
__global__ void k_offsets(int n) {
    __shared__ int s[256];
    __shared__ int basev;
    const int tid = threadIdx.x;
    const int base4 = blockIdx.x * CHUNK + tid * 4;
    int v0 = 0, v1 = 0, v2 = 0, v3 = 0;
    if (base4 + 0 < n) { v0 = g_count[base4 + 0]; g_dinv[base4 + 0] = rsqrtf((float)v0 + 1.f); }
    if (base4 + 1 < n) { v1 = g_count[base4 + 1]; g_dinv[base4 + 1] = rsqrtf((float)v1 + 1.f); }
    if (base4 + 2 < n) { v2 = g_count[base4 + 2]; g_dinv[base4 + 2] = rsqrtf((float)v2 + 1.f); }
    if (base4 + 3 < n) { v3 = g_count[base4 + 3]; g_dinv[base4 + 3] = rsqrtf((float)v3 + 1.f); }
    int tsum = v0 + v1 + v2 + v3;
    s[tid] = tsum;
    __syncthreads();
#pragma unroll
    for (int off = 1; off < 256; off <<= 1) {
        int tmp = (tid >= off) ? s[tid - off] : 0;
        __syncthreads();
        s[tid] += tmp;
        __syncthreads();
    }
    if (tid == 255) basev = atomicAdd(&g_scanbase, s[255]);
    __syncthreads();
    int excl = basev + s[tid] - tsum;
    if (base4 + 0 < n) { g_rowptr[base4 + 0] = excl;                g_cursor[base4 + 0] = excl; }
    if (base4 + 1 < n) { g_rowptr[base4 + 1] = excl + v0;           g_cursor[base4 + 1] = excl + v0; }
    if (base4 + 2 < n) { g_rowptr[base4 + 2] = excl + v0 + v1;      g_cursor[base4 + 2] = excl + v0 + v1; }
    if (base4 + 3 < n) { g_rowptr[base4 + 3] = excl + v0 + v1 + v2; g_cursor[base4 + 3] = excl + v0 + v1 + v2; }
}

// ---------------------------------------------------------------------------
// fatB: blocks with bid%9==0 run the layer-0 GEMM (x @ W0 -> hws, fp32->fp16
// staging); the other 8/9 run the CSR fill. Independent; interleaved by id so
// tensor pipe and L2-atomic path stay busy simultaneously.
// grid = ngemm * 9 exactly.
// ---------------------------------------------------------------------------
__global__ void __launch_bounds__(256, 2)
k_fatB(const float* __restrict__ x, const __half* __restrict__ wt,
       const float* __restrict__ dinv, __half* __restrict__ hws, int n,
       const int* __restrict__ src, const int* __restrict__ dst, int e) {
    extern __shared__ char smem[];
    const int bid = blockIdx.x, tid = threadIdx.x;
    if (bid % 9 == 0) {
        const int row0 = (bid / 9) * 128;
        stage_w(smem, tid, wt);
        stage_a_f32(smem, tid, x, row0, n);
        __syncthreads();
        gemm_core(smem, tid, row0, dinv, hws, n);
    } else {
        const int fid = bid - bid / 9 - 1;               // dense fill-block index
        const int nfill = gridDim.x - (gridDim.x + 8) / 9;
        int i = fid * 256 + tid;
        const int stride = nfill * 256;
        for (; i < e; i += stride) {
            int pos = atomicAdd(&g_cursor[dst[i]], 1);
            g_adj[pos] = src[i];
        }
    }
}

// ---------------------------------------------------------------------------
// Layer 1/2 GEMM (fp16 input; verified round-13 kernel via shared core)
// ---------------------------------------------------------------------------
__global__ void __launch_bounds__(256, 2)
k_gemm_h(const __half* __restrict__ Hh, const __half* __restrict__ wt,
         const float* __restrict__ dinv, __half* __restrict__ hws, int n) {
    extern __shared__ char smem[];
    const int tid = threadIdx.x;
    const int row0 = blockIdx.x * 128;
    stage_w(smem, tid, wt);
    stage_a_f16(smem, tid, Hh, row0, n);
    __syncthreads();
    gemm_core(smem, tid, row0, dinv, hws, n);
}

// ---------------------------------------------------------------------------
// Pull-mode aggregate (fp16 gather, fp32 accumulate), standalone for occupancy.
//   t = dinv[d]*(hws[d] + sum_{s in in(d)} hws[s]) + b
//   FINAL=0: outh[d] = fp16(relu(t));   FINAL=1: outf[d] = t + x[d]
// ---------------------------------------------------------------------------
template <bool FINAL>
__global__ void k_aggregate(const __half* __restrict__ hws, const int* __restrict__ rowptr,
                            const int* __restrict__ cnt, const int* __restrict__ adj,
                            const float* __restrict__ dinv, const float* __restrict__ bias,
                            const float* __restrict__ xres,
                            __half* __restrict__ outh, float* __restrict__ outf, int n) {
    int w = (blockIdx.x * blockDim.x + threadIdx.x) >> 4;
    if (w >= n) return;
    const int lane = threadIdx.x & 15;

    const uint4* base = reinterpret_cast<const uint4*>(hws);
    float acc0[8], acc1[8];
#pragma unroll
    for (int i = 0; i < 8; i++) { acc0[i] = 0.f; acc1[i] = 0.f; }
    add8(acc0, base[(size_t)w * 16 + lane]);  // self-loop

    int j = rowptr[w];
    const int jend = j + cnt[w];
    for (; j + 3 < jend; j += 4) {
        int s0 = __ldg(&adj[j]);
        int s1 = __ldg(&adj[j + 1]);
        int s2 = __ldg(&adj[j + 2]);
        int s3 = __ldg(&adj[j + 3]);
        uint4 a = base[(size_t)s0 * 16 + lane];
        uint4 b = base[(size_t)s1 * 16 + lane];
        uint4 c = base[(size_t)s2 * 16 + lane];
        uint4 d = base[(size_t)s3 * 16 + lane];
        add8(acc0, a); add8(acc1, b); add8(acc0, c); add8(acc1, d);
    }
    for (; j + 1 < jend; j += 2) {
        int s0 = __ldg(&adj[j]);
        int s1 = __ldg(&adj[j + 1]);
        uint4 a = base[(size_t)s0 * 16 + lane];
        uint4 b = base[(size_t)s1 * 16 + lane];
        add8(acc0, a); add8(acc1, b);
    }
    if (j < jend) add8(acc0, base[(size_t)__ldg(&adj[j]) * 16 + lane]);
#pragma unroll
    for (int i = 0; i < 8; i++) acc0[i] += acc1[i];

    const float di = dinv[w];
    const int col = lane * 8;
    float o[8];
#pragma unroll
    for (int i = 0; i < 8; i++) o[i] = fmaf(acc0[i], di, bias[col + i]);

    if (FINAL) {
        const float4* xr = reinterpret_cast<const float4*>(xres + (size_t)w * DD + col);
        float4 x0 = xr[0], x1 = xr[1];
        o[0] += x0.x; o[1] += x0.y; o[2] += x0.z; o[3] += x0.w;
        o[4] += x1.x; o[5] += x1.y; o[6] += x1.z; o[7] += x1.w;
        float4* op = reinterpret_cast<float4*>(outf + (size_t)w * DD + col);
        op[0] = make_float4(o[0], o[1], o[2], o[3]);
        op[1] = make_float4(o[4], o[5], o[6], o[7]);
    } else {
        uint4 hv;
        uint32_t* hp = reinterpret_cast<uint32_t*>(&hv);
#pragma unroll
        for (int i = 0; i < 4; i++) {
            __half2 h2 = __floats2half2_rn(fmaxf(o[2 * i], 0.f), fmaxf(o[2 * i + 1], 0.f));
            hp[i] = *reinterpret_cast<uint32_t*>(&h2);
        }
        reinterpret_cast<uint4*>(outh)[(size_t)w * 16 + lane] = hv;
    }
}

// ---------------------------------------------------------------------------
extern "C" void kernel_launch(void* const* d_in, const int* in_sizes, int n_in,
                              void* d_out, int out_size) {
    const float* x  = (const float*)d_in[0];
    const int*   ei = (const int*)d_in[1];
    const float* W0 = (const float*)d_in[2];
    const float* b0 = (const float*)d_in[3];
    const float* W1 = (const float*)d_in[4];
    const float* b1 = (const float*)d_in[5];
    const float* W2 = (const float*)d_in[6];
    const float* b2 = (const float*)d_in[7];
    float* out = (float*)d_out;

    const int n = in_sizes[0] / DD;
    const int e = in_sizes[1] / 2;
    const int* src = ei;
    const int* dst = ei + e;

    float* d_dinv;
    __half *d_hws, *d_aggh, *d_wt;
    int *d_count, *d_rowptr, *d_adj;
    cudaGetSymbolAddress((void**)&d_hws, g_hwsh);
    cudaGetSymbolAddress((void**)&d_aggh, g_aggh);
    cudaGetSymbolAddress((void**)&d_dinv, g_dinv);
    cudaGetSymbolAddress((void**)&d_count, g_count);
    cudaGetSymbolAddress((void**)&d_rowptr, g_rowptr);
    cudaGetSymbolAddress((void**)&d_adj, g_adj);
    cudaGetSymbolAddress((void**)&d_wt, g_wt);

    cudaFuncSetAttribute(k_fatB,   cudaFuncAttributeMaxDynamicSharedMemorySize, SM_TOT);
    cudaFuncSetAttribute(k_gemm_h, cudaFuncAttributeMaxDynamicSharedMemorySize, SM_TOT);

    const int TB = 256;
    const int nb_gemm = (n + 127) / 128;
    const int nchunks = (n + CHUNK - 1) / CHUNK;
    const int nb_cnt = (e + TB - 1) / TB;
    const long long agg_threads = (long long)n * 16;
    const int nb_agg = (int)((agg_threads + TB - 1) / TB);

    // CSR build overlapped with prep + layer-0 GEMM
    cudaMemsetAsync(d_count, 0, n * sizeof(int));
    k_fatA<<<192 + nb_cnt, TB>>>(W0, W1, W2, d_wt, dst, e);
    k_offsets<<<nchunks, 256>>>(n);
    k_fatB<<<nb_gemm * 9, 256, SM_TOT>>>(x, d_wt, d_dinv, d_hws, n, src, dst, e);

    // Layer 0 aggregate -> fp16 relu activations
    k_aggregate<false><<<nb_agg, TB>>>(d_hws, d_rowptr, d_count, d_adj, d_dinv, b0,
                                       nullptr, d_aggh, nullptr, n);
    // Layer 1
    k_gemm_h<<<nb_gemm, 256, SM_TOT>>>(d_aggh, d_wt + DD * DD, d_dinv, d_hws, n);
    k_aggregate<false><<<nb_agg, TB>>>(d_hws, d_rowptr, d_count, d_adj, d_dinv, b1,
                                       nullptr, d_aggh, nullptr, n);
    // Layer 2 (+x residual fp32 -> d_out)
    k_gemm_h<<<nb_gemm, 256, SM_TOT>>>(d_aggh, d_wt + 2 * DD * DD, d_dinv, d_hws, n);
    k_aggregate<true><<<nb_agg, TB>>>(d_hws, d_rowptr, d_count, d_adj, d_dinv, b2,
                                      x, nullptr, out, n);
}